// round 13
// baseline (speedup 1.0000x reference)
#include <cuda_runtime.h>
#include <cuda_fp16.h>
#include <cstdint>

// ---------------- problem constants ----------------
#define N_NODES 100000
#define N_EDGES 600000
#define NCOLS 544            // 512 xrel + 16 s1 + 16 s2
#define NPAD 576             // padded to 9 * 64-col tiles
#define BCAP 48              // bucket capacity per dst (Poisson(6), max ~25)

// ---------------- device scratch (no allocs allowed) ----------------
__device__ __align__(16) __half g_Bh[NPAD * 128];              // B fp16 [j][k]
__device__ __align__(16) __half g_xrelh[(size_t)N_NODES * 512];// [(n*4+r)][128] fp16
__device__ __align__(16) float g_s1[N_NODES * 16];             // [n][r][h]
__device__ __align__(16) float g_s2[N_NODES * 16];             // [n][r][h]
__device__ int g_cnt[N_NODES];                                 // per-dst degree
__device__ int g_bucket[(size_t)N_NODES * BCAP];               // packed src*4+et
__device__ int g_is64;

#define CP_ASYNC16(dst, src) \
    asm volatile("cp.async.cg.shared.global [%0], [%1], 16;" :: "r"(dst), "l"(src) : "memory")
#define CP_COMMIT()  asm volatile("cp.async.commit_group;" ::: "memory")
#define CP_WAIT(n)   asm volatile("cp.async.wait_group %0;" :: "n"(n) : "memory")

// ---------------- merged prologue: prep_B + zero counts + dtype sniff --------
// blocks [0, 288): build g_Bh. blocks [288, 679): zero g_cnt (+ thread 0 sniff)
#define PREP_BLOCKS 288
__global__ void prep_detect_zero(const float* __restrict__ W,
                                 const float* __restrict__ attn,
                                 const unsigned* __restrict__ ei) {
    if (blockIdx.x < PREP_BLOCKS) {
        int id = blockIdx.x * blockDim.x + threadIdx.x;
        if (id >= NPAD * 128) return;
        int j = id >> 7, k = id & 127;
        float v = 0.0f;
        if (j < 512) {
            int r = j >> 7, o = j & 127;
            v = W[(r * 128 + k) * 128 + o];
        } else if (j < NCOLS) {
            int j2 = j - 512;
            int half = j2 >> 4;
            int rh = j2 & 15;
            int r = rh >> 2, h = rh & 3;
            const float* wp = W + (r * 128 + k) * 128 + h * 32;
            const float* ap = attn + rh * 64 + half * 32;
            float s = 0.0f;
#pragma unroll
            for (int d = 0; d < 32; d++) s += wp[d] * ap[d];
            v = s;
        }
        g_Bh[id] = __float2half(v);
    } else {
        int i = (blockIdx.x - PREP_BLOCKS) * blockDim.x + threadIdx.x;
        if (i < N_NODES) g_cnt[i] = 0;
        if (i == 0) {
            int is64 = 1;
            for (int k = 0; k < 16; k++)
                if (ei[2 * k + 1] != 0u) is64 = 0;
            g_is64 = is64;
        }
    }
}

__device__ __forceinline__ void ldsm4(uint32_t& r0, uint32_t& r1,
                                      uint32_t& r2, uint32_t& r3, uint32_t addr) {
    asm volatile("ldmatrix.sync.aligned.m8n8.x4.shared.b16 {%0,%1,%2,%3}, [%4];"
                 : "=r"(r0), "=r"(r1), "=r"(r2), "=r"(r3) : "r"(addr));
}

__device__ __forceinline__ void mma_f16(float* c, const uint32_t* a,
                                        uint32_t b0, uint32_t b1) {
    asm volatile("mma.sync.aligned.m16n8k16.row.col.f32.f16.f16.f32 "
                 "{%0,%1,%2,%3}, {%4,%5,%6,%7}, {%8,%9}, {%0,%1,%2,%3};"
                 : "+f"(c[0]), "+f"(c[1]), "+f"(c[2]), "+f"(c[3])
                 : "r"(a[0]), "r"(a[1]), "r"(a[2]), "r"(a[3]), "r"(b0), "r"(b1));
}

// ---------------- GEMM + embedded edge decode, BN=64, 2 CTAs/SM --------------
// grid=782, 256 thr (4 m-warps x 2 n-warps, warp tile 32x32). BM=128, BN=64,
// 9 col-iters. A fp16 resident (32KB); B double-buffered cp.async (2x16KB).
// Each CTA also decodes+buckets 768 edges, overlapped with the mainloop.
#define SMEM_TOT (64 * 1024)
#define EDGES_PER_CTA 768
__global__ __launch_bounds__(256, 2) void gemm_hc(const float* __restrict__ x,
                                                  const void* __restrict__ ei_raw,
                                                  const void* __restrict__ et_raw) {
    extern __shared__ __align__(16) char smem[];
    const uint32_t sb = (uint32_t)__cvta_generic_to_shared(smem);
    const int t = threadIdx.x;
    const int lane = t & 31, wid = t >> 5;
    const int wm = wid & 3, wn = wid >> 2;
    const int rowBase = blockIdx.x * 128;

    // ---- load + convert A tile once (128 rows x 128 k) ----
#pragma unroll
    for (int i = 0; i < 8; i++) {
        int u = i * 256 + t;
        int r = u >> 4, c = u & 15;
        int row = rowBase + r;
        float4 v0 = make_float4(0.f, 0.f, 0.f, 0.f), v1 = v0;
        if (row < N_NODES) {
            v0 = *(const float4*)(x + (size_t)row * 128 + c * 8);
            v1 = *(const float4*)(x + (size_t)row * 128 + c * 8 + 4);
        }
        __half2 h0 = __floats2half2_rn(v0.x, v0.y);
        __half2 h1 = __floats2half2_rn(v0.z, v0.w);
        __half2 h2 = __floats2half2_rn(v1.x, v1.y);
        __half2 h3 = __floats2half2_rn(v1.z, v1.w);
        uint4 hi = make_uint4(*(uint32_t*)&h0, *(uint32_t*)&h1,
                              *(uint32_t*)&h2, *(uint32_t*)&h3);
        int sw = (c & 8) | ((c & 7) ^ (r & 7));
        *(uint4*)(smem + (r * 16 + sw) * 16) = hi;
    }

    // ---- issue B tile 0 (64 rows x 128 k = 1024 uint4) ----
#pragma unroll
    for (int i = 0; i < 4; i++) {
        int u = i * 256 + t;
        int n = u >> 4, c = u & 15;
        uint32_t dst = sb + (uint32_t)(2048 + n * 16 + ((c & 8) | ((c & 7) ^ (n & 7)))) * 16;
        CP_ASYNC16(dst, (const char*)(g_Bh + n * 128 + c * 8));
    }
    CP_COMMIT();

    // ---- embedded edge decode: 3 edges/thread, overlaps with mainloop ----
    {
        const int is64 = g_is64;
        const int ebase = blockIdx.x * EDGES_PER_CTA;
#pragma unroll 1
        for (int i = 0; i < 3; i++) {
            int e = ebase + i * 256 + t;
            if (e < N_EDGES) {
                int src, dst, et;
                if (is64) {
                    const long long* ei = (const long long*)ei_raw;
                    const long long* etp = (const long long*)et_raw;
                    src = (int)ei[e];
                    dst = (int)ei[N_EDGES + e];
                    et  = (int)etp[e];
                } else {
                    const int* ei = (const int*)ei_raw;
                    const int* etp = (const int*)et_raw;
                    src = ei[e];
                    dst = ei[N_EDGES + e];
                    et  = etp[e];
                }
                int slot = atomicAdd(&g_cnt[dst], 1);
                if (slot < BCAP) g_bucket[(size_t)dst * BCAP + slot] = src * 4 + et;
            }
        }
    }

    for (int it = 0; it < 9; it++) {
        if (it < 8) {
            const int nb = (it + 1) & 1;
            const int colN = (it + 1) * 64;
#pragma unroll
            for (int i = 0; i < 4; i++) {
                int u = i * 256 + t;
                int n = u >> 4, c = u & 15;
                uint32_t dst = sb + (uint32_t)(2048 + nb * 1024 + n * 16 +
                                               ((c & 8) | ((c & 7) ^ (n & 7)))) * 16;
                CP_ASYNC16(dst, (const char*)(g_Bh + (colN + n) * 128 + c * 8));
            }
            CP_COMMIT();
            CP_WAIT(1);
        } else {
            CP_WAIT(0);
        }
        __syncthreads();

        const uint32_t bBase = 2048 + (it & 1) * 1024;
        float acc[2][4][4];
#pragma unroll
        for (int mt = 0; mt < 2; mt++)
#pragma unroll
            for (int nt = 0; nt < 4; nt++)
#pragma unroll
                for (int i = 0; i < 4; i++) acc[mt][nt][i] = 0.0f;

#pragma unroll
        for (int s = 0; s < 8; s++) {
            uint32_t Ah[2][4], Bh[4][2];
            const int mat = lane >> 3;
#pragma unroll
            for (int mt = 0; mt < 2; mt++) {
                int r = wm * 32 + mt * 16 + (mat & 1) * 8 + (lane & 7);
                int c = s * 2 + (mat >> 1);
                int sw = (c & 8) | ((c & 7) ^ (r & 7));
                ldsm4(Ah[mt][0], Ah[mt][1], Ah[mt][2], Ah[mt][3],
                      sb + (uint32_t)(r * 16 + sw) * 16);
            }
#pragma unroll
            for (int p = 0; p < 2; p++) {
                int n = wn * 32 + p * 16 + (mat >> 1) * 8 + (lane & 7);
                int c = s * 2 + (mat & 1);
                int sw = (c & 8) | ((c & 7) ^ (n & 7));
                ldsm4(Bh[p * 2][0], Bh[p * 2][1], Bh[p * 2 + 1][0], Bh[p * 2 + 1][1],
                      sb + (uint32_t)(bBase + n * 16 + sw) * 16);
            }
#pragma unroll
            for (int mt = 0; mt < 2; mt++)
#pragma unroll
                for (int nt = 0; nt < 4; nt++)
                    mma_f16(acc[mt][nt], Ah[mt], Bh[nt][0], Bh[nt][1]);
        }

        // ---- epilogue for this 64-col tile ----
        const int colBase = it * 64;
#pragma unroll
        for (int mt = 0; mt < 2; mt++) {
            int row0 = rowBase + wm * 32 + mt * 16 + (lane >> 2);
#pragma unroll
            for (int nt = 0; nt < 4; nt++) {
                int lc = wn * 32 + nt * 8 + (lane & 3) * 2;
#pragma unroll
                for (int half = 0; half < 2; half++) {
                    int row = row0 + half * 8;
                    if (row >= N_NODES) continue;
                    float f0 = acc[mt][nt][half * 2];
                    float f1 = acc[mt][nt][half * 2 + 1];
                    if (it < 8) {
                        *(__half2*)(g_xrelh + (size_t)row * 512 + colBase + lc) =
                            __floats2half2_rn(f0, f1);
                    } else {
                        if (lc < 16)
                            *(float2*)(g_s1 + row * 16 + lc) = make_float2(f0, f1);
                        else if (lc < 32)
                            *(float2*)(g_s2 + row * 16 + (lc - 16)) = make_float2(f0, f1);
                    }
                }
            }
        }
        __syncthreads();
    }
}

// ---------------- fused edge pass: per-(dst,rel) softmax + gather, warp/dst ---
// 512 thr = 16 warps/block. Phase A lane-parallel over (edge, head); phase B
// MLP-4 unrolled gather. Per-warp smem: 48 packed ids + 48x4 ev floats.
__global__ __launch_bounds__(512) void edge_fused(float* __restrict__ out) {
    __shared__ int   sm_pk[16][BCAP];
    __shared__ float sm_ev[16][BCAP * 4];
    int w = threadIdx.x >> 5;
    int d = blockIdx.x * 16 + w;
    if (d >= N_NODES) return;
    int lane = threadIdx.x & 31;
    int deg = g_cnt[d];
    if (deg > BCAP) deg = BCAP;
    const int* bk = g_bucket + (size_t)d * BCAP;

    // ---- phase A: lane-parallel logits+exp (8 edges x 4 heads per step) ----
    int ie = lane >> 2;          // edge sub-index 0..7
    int hA = lane & 3;           // head for phase A
    for (int base = 0; base < deg; base += 8) {
        int i = base + ie;
        if (i < deg) {
            int packed = bk[i];
            float s1v = g_s1[packed * 4 + hA];
            float s2v = g_s2[d * 16 + (packed & 3) * 4 + hA];
            float al = s1v + s2v;
            al = al > 0.f ? al : 0.2f * al;
            sm_ev[w][i * 4 + hA] = __expf(al);
            if (hA == 0) sm_pk[w][i] = packed;
        }
    }
    __syncwarp();

    // ---- per-relation denominators from smem (head for phase B layout) ----
    int h = lane >> 3;
    float den[4] = {0.f, 0.f, 0.f, 0.f};
    for (int i = 0; i < deg; i++)
        den[sm_pk[w][i] & 3] += sm_ev[w][i * 4 + h];
    float rden[4];
#pragma unroll
    for (int r = 0; r < 4; r++)
        rden[r] = (den[r] > 0.f) ? __frcp_rn(den[r]) : 0.0f;

    // ---- phase B: MLP-4 weighted gather-accumulate of fp16 xrel rows ----
    float a0 = 0.f, a1 = 0.f, a2 = 0.f, a3 = 0.f;
    const uint2* xr = reinterpret_cast<const uint2*>(g_xrelh);
    int i = 0;
    for (; i + 4 <= deg; i += 4) {
        int p0 = sm_pk[w][i], p1 = sm_pk[w][i + 1];
        int p2 = sm_pk[w][i + 2], p3 = sm_pk[w][i + 3];
        uint2 r0 = xr[(size_t)p0 * 32 + lane];
        uint2 r1 = xr[(size_t)p1 * 32 + lane];
        uint2 r2 = xr[(size_t)p2 * 32 + lane];
        uint2 r3 = xr[(size_t)p3 * 32 + lane];
        float w0 = sm_ev[w][(i + 0) * 4 + h] * rden[p0 & 3];
        float w1 = sm_ev[w][(i + 1) * 4 + h] * rden[p1 & 3];
        float w2 = sm_ev[w][(i + 2) * 4 + h] * rden[p2 & 3];
        float w3 = sm_ev[w][(i + 3) * 4 + h] * rden[p3 & 3];
        float2 f;
        f = __half22float2(*(__half2*)&r0.x); a0 += f.x * w0; a1 += f.y * w0;
        f = __half22float2(*(__half2*)&r0.y); a2 += f.x * w0; a3 += f.y * w0;
        f = __half22float2(*(__half2*)&r1.x); a0 += f.x * w1; a1 += f.y * w1;
        f = __half22float2(*(__half2*)&r1.y); a2 += f.x * w1; a3 += f.y * w1;
        f = __half22float2(*(__half2*)&r2.x); a0 += f.x * w2; a1 += f.y * w2;
        f = __half22float2(*(__half2*)&r2.y); a2 += f.x * w2; a3 += f.y * w2;
        f = __half22float2(*(__half2*)&r3.x); a0 += f.x * w3; a1 += f.y * w3;
        f = __half22float2(*(__half2*)&r3.y); a2 += f.x * w3; a3 += f.y * w3;
    }
    for (; i < deg; i++) {
        int p = sm_pk[w][i];
        float wgt = sm_ev[w][i * 4 + h] * rden[p & 3];
        uint2 raw = xr[(size_t)p * 32 + lane];
        float2 f0 = __half22float2(*(__half2*)&raw.x);
        float2 f1 = __half22float2(*(__half2*)&raw.y);
        a0 += f0.x * wgt; a1 += f0.y * wgt; a2 += f1.x * wgt; a3 += f1.y * wgt;
    }
    reinterpret_cast<float4*>(out + (size_t)d * 128)[lane] = make_float4(a0, a1, a2, a3);
}

// ---------------- launch ----------------
extern "C" void kernel_launch(void* const* d_in, const int* in_sizes, int n_in,
                              void* d_out, int out_size) {
    const float* x    = (const float*)d_in[0];
    const void*  ei   = d_in[1];
    const void*  etyp = d_in[2];
    const float* W    = (const float*)d_in[3];
    const float* attn = (const float*)d_in[4];
    float*       out  = (float*)d_out;

    cudaFuncSetAttribute(gemm_hc, cudaFuncAttributeMaxDynamicSharedMemorySize, SMEM_TOT);

    int zblocks = (N_NODES + 255) / 256;
    prep_detect_zero<<<PREP_BLOCKS + zblocks, 256>>>(W, attn, (const unsigned*)ei);
    gemm_hc<<<(N_NODES + 127) / 128, 256, SMEM_TOT>>>(x, ei, etyp);
    edge_fused<<<(N_NODES + 15) / 16, 512>>>(out);
}

// round 14
// speedup vs baseline: 1.0004x; 1.0004x over previous
#include <cuda_runtime.h>
#include <cuda_fp16.h>
#include <cstdint>

// ---------------- problem constants ----------------
#define N_NODES 100000
#define N_EDGES 600000
#define NCOLS 544            // 512 xrel + 16 s1 + 16 s2
#define NPAD 576             // padded to 9 * 64-col tiles
#define BCAP 48              // bucket capacity per dst (Poisson(6), max ~25)

// ---------------- device scratch (no allocs allowed) ----------------
__device__ __align__(16) __half g_Bh[NPAD * 128];              // B fp16 [j][k]
__device__ __align__(16) __half g_xrelh[(size_t)N_NODES * 512];// [(n*4+r)][128] fp16
__device__ __align__(16) float g_s1[N_NODES * 16];             // [n][r][h]
__device__ __align__(16) float g_s2[N_NODES * 16];             // [n][r][h]
__device__ int g_cnt[N_NODES];                                 // per-dst degree
__device__ int g_bucket[(size_t)N_NODES * BCAP];               // packed src*4+et
__device__ int g_is64;

#define CP_ASYNC16(dst, src) \
    asm volatile("cp.async.cg.shared.global [%0], [%1], 16;" :: "r"(dst), "l"(src) : "memory")
#define CP_COMMIT()  asm volatile("cp.async.commit_group;" ::: "memory")
#define CP_WAIT(n)   asm volatile("cp.async.wait_group %0;" :: "n"(n) : "memory")

// ---------------- merged prologue ----------------
// blocks [0,64):   W -> g_Bh transpose via smem tiles (coalesced both sides)
// blocks [64,96):  attn-derived cols 512..543 + zero pad 544..575
// blocks [96,487): zero g_cnt (+ thread 0 dtype sniff)
#define WT_BLOCKS 64
#define AT_BLOCKS 32
#define PREP_BLOCKS (WT_BLOCKS + AT_BLOCKS)
__global__ void prep_detect_zero(const float* __restrict__ W,
                                 const float* __restrict__ attn,
                                 const unsigned* __restrict__ ei) {
    if (blockIdx.x < WT_BLOCKS) {
        // 32x32 tile transpose: W[r][k][o] -> g_Bh[(r*128+o)*128 + k]
        __shared__ float tile[32][33];
        int tt = blockIdx.x;
        int r  = tt >> 4;            // relation 0..3
        int kt = (tt >> 2) & 3;      // k tile
        int ot = tt & 3;             // o tile
        int ty = threadIdx.x >> 5;   // 0..7
        int tx = threadIdx.x & 31;
#pragma unroll
        for (int s = 0; s < 4; s++) {
            int k = kt * 32 + ty + s * 8;
            int o = ot * 32 + tx;
            tile[ty + s * 8][tx] = W[(r * 128 + k) * 128 + o];
        }
        __syncthreads();
#pragma unroll
        for (int s = 0; s < 4; s++) {
            int o = ot * 32 + ty + s * 8;
            int k = kt * 32 + tx;
            g_Bh[(r * 128 + o) * 128 + k] = __float2half(tile[tx][ty + s * 8]);
        }
    } else if (blockIdx.x < PREP_BLOCKS) {
        // cols 512..543: dot(W[r][k][h*32..], attn[rh][half*32..]); 544..575: 0
        int id = (blockIdx.x - WT_BLOCKS) * 256 + threadIdx.x;  // 8192 elems
        int j2 = id >> 7;            // 0..63
        int k = id & 127;
        float v = 0.0f;
        if (j2 < 32) {
            int half = j2 >> 4;
            int rh = j2 & 15;
            int r = rh >> 2, h = rh & 3;
            const float* wp = W + (r * 128 + k) * 128 + h * 32;
            const float* ap = attn + rh * 64 + half * 32;
            float s = 0.0f;
#pragma unroll
            for (int d = 0; d < 32; d++) s += wp[d] * ap[d];
            v = s;
        }
        g_Bh[(512 + j2) * 128 + k] = __float2half(v);
    } else {
        int i = (blockIdx.x - PREP_BLOCKS) * 256 + threadIdx.x;
        if (i < N_NODES) g_cnt[i] = 0;
        if (i == 0) {
            int is64 = 1;
            for (int k = 0; k < 16; k++)
                if (ei[2 * k + 1] != 0u) is64 = 0;
            g_is64 = is64;
        }
    }
}

// ---------------- decode + bucket (separate: must NOT pollute gemm ramp) -----
__global__ void decode_bucket_kernel(const void* __restrict__ ei_raw,
                                     const void* __restrict__ et_raw) {
    int e = blockIdx.x * blockDim.x + threadIdx.x;
    if (e >= N_EDGES) return;
    int src, dst, et;
    if (g_is64) {
        const long long* ei = (const long long*)ei_raw;
        const long long* etp = (const long long*)et_raw;
        src = (int)ei[e];
        dst = (int)ei[N_EDGES + e];
        et  = (int)etp[e];
    } else {
        const int* ei = (const int*)ei_raw;
        const int* etp = (const int*)et_raw;
        src = ei[e];
        dst = ei[N_EDGES + e];
        et  = etp[e];
    }
    int slot = atomicAdd(&g_cnt[dst], 1);
    if (slot < BCAP) g_bucket[(size_t)dst * BCAP + slot] = src * 4 + et;
}

__device__ __forceinline__ void ldsm4(uint32_t& r0, uint32_t& r1,
                                      uint32_t& r2, uint32_t& r3, uint32_t addr) {
    asm volatile("ldmatrix.sync.aligned.m8n8.x4.shared.b16 {%0,%1,%2,%3}, [%4];"
                 : "=r"(r0), "=r"(r1), "=r"(r2), "=r"(r3) : "r"(addr));
}

__device__ __forceinline__ void mma_f16(float* c, const uint32_t* a,
                                        uint32_t b0, uint32_t b1) {
    asm volatile("mma.sync.aligned.m16n8k16.row.col.f32.f16.f16.f32 "
                 "{%0,%1,%2,%3}, {%4,%5,%6,%7}, {%8,%9}, {%0,%1,%2,%3};"
                 : "+f"(c[0]), "+f"(c[1]), "+f"(c[2]), "+f"(c[3])
                 : "r"(a[0]), "r"(a[1]), "r"(a[2]), "r"(a[3]), "r"(b0), "r"(b1));
}

// ---------------- GEMM: persistent row-tile, BN=64, 2 CTAs/SM ----------------
#define SMEM_TOT (64 * 1024)
__global__ __launch_bounds__(256, 2) void gemm_hc(const float* __restrict__ x) {
    extern __shared__ __align__(16) char smem[];
    const uint32_t sb = (uint32_t)__cvta_generic_to_shared(smem);
    const int t = threadIdx.x;
    const int lane = t & 31, wid = t >> 5;
    const int wm = wid & 3, wn = wid >> 2;
    const int rowBase = blockIdx.x * 128;

    // ---- load + convert A tile once (128 rows x 128 k) ----
#pragma unroll
    for (int i = 0; i < 8; i++) {
        int u = i * 256 + t;
        int r = u >> 4, c = u & 15;
        int row = rowBase + r;
        float4 v0 = make_float4(0.f, 0.f, 0.f, 0.f), v1 = v0;
        if (row < N_NODES) {
            v0 = *(const float4*)(x + (size_t)row * 128 + c * 8);
            v1 = *(const float4*)(x + (size_t)row * 128 + c * 8 + 4);
        }
        __half2 h0 = __floats2half2_rn(v0.x, v0.y);
        __half2 h1 = __floats2half2_rn(v0.z, v0.w);
        __half2 h2 = __floats2half2_rn(v1.x, v1.y);
        __half2 h3 = __floats2half2_rn(v1.z, v1.w);
        uint4 hi = make_uint4(*(uint32_t*)&h0, *(uint32_t*)&h1,
                              *(uint32_t*)&h2, *(uint32_t*)&h3);
        int sw = (c & 8) | ((c & 7) ^ (r & 7));
        *(uint4*)(smem + (r * 16 + sw) * 16) = hi;
    }

    // ---- issue B tile 0 (64 rows x 128 k = 1024 uint4) ----
#pragma unroll
    for (int i = 0; i < 4; i++) {
        int u = i * 256 + t;
        int n = u >> 4, c = u & 15;
        uint32_t dst = sb + (uint32_t)(2048 + n * 16 + ((c & 8) | ((c & 7) ^ (n & 7)))) * 16;
        CP_ASYNC16(dst, (const char*)(g_Bh + n * 128 + c * 8));
    }
    CP_COMMIT();

    for (int it = 0; it < 9; it++) {
        if (it < 8) {
            const int nb = (it + 1) & 1;
            const int colN = (it + 1) * 64;
#pragma unroll
            for (int i = 0; i < 4; i++) {
                int u = i * 256 + t;
                int n = u >> 4, c = u & 15;
                uint32_t dst = sb + (uint32_t)(2048 + nb * 1024 + n * 16 +
                                               ((c & 8) | ((c & 7) ^ (n & 7)))) * 16;
                CP_ASYNC16(dst, (const char*)(g_Bh + (colN + n) * 128 + c * 8));
            }
            CP_COMMIT();
            CP_WAIT(1);
        } else {
            CP_WAIT(0);
        }
        __syncthreads();

        const uint32_t bBase = 2048 + (it & 1) * 1024;
        float acc[2][4][4];
#pragma unroll
        for (int mt = 0; mt < 2; mt++)
#pragma unroll
            for (int nt = 0; nt < 4; nt++)
#pragma unroll
                for (int i = 0; i < 4; i++) acc[mt][nt][i] = 0.0f;

#pragma unroll
        for (int s = 0; s < 8; s++) {
            uint32_t Ah[2][4], Bh[4][2];
            const int mat = lane >> 3;
#pragma unroll
            for (int mt = 0; mt < 2; mt++) {
                int r = wm * 32 + mt * 16 + (mat & 1) * 8 + (lane & 7);
                int c = s * 2 + (mat >> 1);
                int sw = (c & 8) | ((c & 7) ^ (r & 7));
                ldsm4(Ah[mt][0], Ah[mt][1], Ah[mt][2], Ah[mt][3],
                      sb + (uint32_t)(r * 16 + sw) * 16);
            }
#pragma unroll
            for (int p = 0; p < 2; p++) {
                int n = wn * 32 + p * 16 + (mat >> 1) * 8 + (lane & 7);
                int c = s * 2 + (mat & 1);
                int sw = (c & 8) | ((c & 7) ^ (n & 7));
                ldsm4(Bh[p * 2][0], Bh[p * 2][1], Bh[p * 2 + 1][0], Bh[p * 2 + 1][1],
                      sb + (uint32_t)(bBase + n * 16 + sw) * 16);
            }
#pragma unroll
            for (int mt = 0; mt < 2; mt++)
#pragma unroll
                for (int nt = 0; nt < 4; nt++)
                    mma_f16(acc[mt][nt], Ah[mt], Bh[nt][0], Bh[nt][1]);
        }

        // ---- epilogue for this 64-col tile ----
        const int colBase = it * 64;
#pragma unroll
        for (int mt = 0; mt < 2; mt++) {
            int row0 = rowBase + wm * 32 + mt * 16 + (lane >> 2);
#pragma unroll
            for (int nt = 0; nt < 4; nt++) {
                int lc = wn * 32 + nt * 8 + (lane & 3) * 2;
#pragma unroll
                for (int half = 0; half < 2; half++) {
                    int row = row0 + half * 8;
                    if (row >= N_NODES) continue;
                    float f0 = acc[mt][nt][half * 2];
                    float f1 = acc[mt][nt][half * 2 + 1];
                    if (it < 8) {
                        *(__half2*)(g_xrelh + (size_t)row * 512 + colBase + lc) =
                            __floats2half2_rn(f0, f1);
                    } else {
                        if (lc < 16)
                            *(float2*)(g_s1 + row * 16 + lc) = make_float2(f0, f1);
                        else if (lc < 32)
                            *(float2*)(g_s2 + row * 16 + (lc - 16)) = make_float2(f0, f1);
                    }
                }
            }
        }
        __syncthreads();
    }
}

// ---------------- fused edge pass: per-(dst,rel) softmax + gather, warp/dst ---
__global__ __launch_bounds__(512) void edge_fused(float* __restrict__ out) {
    __shared__ int   sm_pk[16][BCAP];
    __shared__ float sm_ev[16][BCAP * 4];
    int w = threadIdx.x >> 5;
    int d = blockIdx.x * 16 + w;
    if (d >= N_NODES) return;
    int lane = threadIdx.x & 31;
    int deg = g_cnt[d];
    if (deg > BCAP) deg = BCAP;
    const int* bk = g_bucket + (size_t)d * BCAP;

    // ---- phase A: lane-parallel logits+exp (8 edges x 4 heads per step) ----
    int ie = lane >> 2;
    int hA = lane & 3;
    for (int base = 0; base < deg; base += 8) {
        int i = base + ie;
        if (i < deg) {
            int packed = bk[i];
            float s1v = g_s1[packed * 4 + hA];
            float s2v = g_s2[d * 16 + (packed & 3) * 4 + hA];
            float al = s1v + s2v;
            al = al > 0.f ? al : 0.2f * al;
            sm_ev[w][i * 4 + hA] = __expf(al);
            if (hA == 0) sm_pk[w][i] = packed;
        }
    }
    __syncwarp();

    // ---- per-relation denominators ----
    int h = lane >> 3;
    float den[4] = {0.f, 0.f, 0.f, 0.f};
    for (int i = 0; i < deg; i++)
        den[sm_pk[w][i] & 3] += sm_ev[w][i * 4 + h];
    float rden[4];
#pragma unroll
    for (int r = 0; r < 4; r++)
        rden[r] = (den[r] > 0.f) ? __frcp_rn(den[r]) : 0.0f;

    // ---- phase B: MLP-4 weighted gather-accumulate ----
    float a0 = 0.f, a1 = 0.f, a2 = 0.f, a3 = 0.f;
    const uint2* xr = reinterpret_cast<const uint2*>(g_xrelh);
    int i = 0;
    for (; i + 4 <= deg; i += 4) {
        int p0 = sm_pk[w][i], p1 = sm_pk[w][i + 1];
        int p2 = sm_pk[w][i + 2], p3 = sm_pk[w][i + 3];
        uint2 r0 = xr[(size_t)p0 * 32 + lane];
        uint2 r1 = xr[(size_t)p1 * 32 + lane];
        uint2 r2 = xr[(size_t)p2 * 32 + lane];
        uint2 r3 = xr[(size_t)p3 * 32 + lane];
        float w0 = sm_ev[w][(i + 0) * 4 + h] * rden[p0 & 3];
        float w1 = sm_ev[w][(i + 1) * 4 + h] * rden[p1 & 3];
        float w2 = sm_ev[w][(i + 2) * 4 + h] * rden[p2 & 3];
        float w3 = sm_ev[w][(i + 3) * 4 + h] * rden[p3 & 3];
        float2 f;
        f = __half22float2(*(__half2*)&r0.x); a0 += f.x * w0; a1 += f.y * w0;
        f = __half22float2(*(__half2*)&r0.y); a2 += f.x * w0; a3 += f.y * w0;
        f = __half22float2(*(__half2*)&r1.x); a0 += f.x * w1; a1 += f.y * w1;
        f = __half22float2(*(__half2*)&r1.y); a2 += f.x * w1; a3 += f.y * w1;
        f = __half22float2(*(__half2*)&r2.x); a0 += f.x * w2; a1 += f.y * w2;
        f = __half22float2(*(__half2*)&r2.y); a2 += f.x * w2; a3 += f.y * w2;
        f = __half22float2(*(__half2*)&r3.x); a0 += f.x * w3; a1 += f.y * w3;
        f = __half22float2(*(__half2*)&r3.y); a2 += f.x * w3; a3 += f.y * w3;
    }
    for (; i < deg; i++) {
        int p = sm_pk[w][i];
        float wgt = sm_ev[w][i * 4 + h] * rden[p & 3];
        uint2 raw = xr[(size_t)p * 32 + lane];
        float2 f0 = __half22float2(*(__half2*)&raw.x);
        float2 f1 = __half22float2(*(__half2*)&raw.y);
        a0 += f0.x * wgt; a1 += f0.y * wgt; a2 += f1.x * wgt; a3 += f1.y * wgt;
    }
    reinterpret_cast<float4*>(out + (size_t)d * 128)[lane] = make_float4(a0, a1, a2, a3);
}

// ---------------- launch ----------------
extern "C" void kernel_launch(void* const* d_in, const int* in_sizes, int n_in,
                              void* d_out, int out_size) {
    const float* x    = (const float*)d_in[0];
    const void*  ei   = d_in[1];
    const void*  etyp = d_in[2];
    const float* W    = (const float*)d_in[3];
    const float* attn = (const float*)d_in[4];
    float*       out  = (float*)d_out;

    cudaFuncSetAttribute(gemm_hc, cudaFuncAttributeMaxDynamicSharedMemorySize, SMEM_TOT);

    int zblocks = (N_NODES + 255) / 256;
    prep_detect_zero<<<PREP_BLOCKS + zblocks, 256>>>(W, attn, (const unsigned*)ei);
    decode_bucket_kernel<<<(N_EDGES + 255) / 256, 256>>>(ei, etyp);
    gemm_hc<<<(N_NODES + 127) / 128, 256, SMEM_TOT>>>(x);
    edge_fused<<<(N_NODES + 15) / 16, 512>>>(out);
}

// round 15
// speedup vs baseline: 1.2265x; 1.2261x over previous
#include <cuda_runtime.h>
#include <cuda_fp16.h>
#include <cstdint>

// ---------------- problem constants ----------------
#define N_NODES 100000
#define N_EDGES 600000
#define NCOLS 544            // 512 xrel + 16 s1 + 16 s2
#define NPAD 576             // padded to 9 * 64-col tiles
#define BCAP 48              // bucket capacity per dst (Poisson(6), max ~25)

// ---------------- device scratch (no allocs allowed) ----------------
__device__ __align__(16) __half g_Bh[NPAD * 128];              // B fp16 [j][k]
__device__ __align__(16) __half g_xrelh[(size_t)N_NODES * 512];// [(n*4+r)][128] fp16
__device__ __align__(16) float g_s1[N_NODES * 16];             // [n][r][h]
__device__ __align__(16) float g_s2[N_NODES * 16];             // [n][r][h]
__device__ int g_cnt[N_NODES];                                 // per-dst degree
__device__ int g_bucket[(size_t)N_NODES * BCAP];               // packed src*4+et
__device__ int g_is64;

#define CP_ASYNC16(dst, src) \
    asm volatile("cp.async.cg.shared.global [%0], [%1], 16;" :: "r"(dst), "l"(src) : "memory")
#define CP_COMMIT()  asm volatile("cp.async.commit_group;" ::: "memory")
#define CP_WAIT(n)   asm volatile("cp.async.wait_group %0;" :: "n"(n) : "memory")

// ---------------- merged prologue ----------------
// blocks [0,64):   W -> g_Bh transpose via smem tiles (coalesced both sides)
// blocks [64,96):  attn-derived cols 512..543 + zero pad 544..575
// blocks [96,...): zero g_cnt (+ thread 0 dtype sniff)
#define WT_BLOCKS 64
#define AT_BLOCKS 32
#define PREP_BLOCKS (WT_BLOCKS + AT_BLOCKS)
__global__ void prep_detect_zero(const float* __restrict__ W,
                                 const float* __restrict__ attn,
                                 const unsigned* __restrict__ ei) {
    if (blockIdx.x < WT_BLOCKS) {
        __shared__ float tile[32][33];
        int tt = blockIdx.x;
        int r  = tt >> 4;
        int kt = (tt >> 2) & 3;
        int ot = tt & 3;
        int ty = threadIdx.x >> 5;
        int tx = threadIdx.x & 31;
#pragma unroll
        for (int s = 0; s < 4; s++) {
            int k = kt * 32 + ty + s * 8;
            int o = ot * 32 + tx;
            tile[ty + s * 8][tx] = W[(r * 128 + k) * 128 + o];
        }
        __syncthreads();
#pragma unroll
        for (int s = 0; s < 4; s++) {
            int o = ot * 32 + ty + s * 8;
            int k = kt * 32 + tx;
            g_Bh[(r * 128 + o) * 128 + k] = __float2half(tile[tx][ty + s * 8]);
        }
    } else if (blockIdx.x < PREP_BLOCKS) {
        int id = (blockIdx.x - WT_BLOCKS) * 256 + threadIdx.x;
        int j2 = id >> 7;
        int k = id & 127;
        float v = 0.0f;
        if (j2 < 32) {
            int half = j2 >> 4;
            int rh = j2 & 15;
            int r = rh >> 2, h = rh & 3;
            const float* wp = W + (r * 128 + k) * 128 + h * 32;
            const float* ap = attn + rh * 64 + half * 32;
            float s = 0.0f;
#pragma unroll
            for (int d = 0; d < 32; d++) s += wp[d] * ap[d];
            v = s;
        }
        g_Bh[(512 + j2) * 128 + k] = __float2half(v);
    } else {
        int i = (blockIdx.x - PREP_BLOCKS) * 256 + threadIdx.x;
        if (i < N_NODES) g_cnt[i] = 0;
        if (i == 0) {
            int is64 = 1;
            for (int k = 0; k < 16; k++)
                if (ei[2 * k + 1] != 0u) is64 = 0;
            g_is64 = is64;
        }
    }
}

// ---------------- decode + bucket ----------------
__global__ void decode_bucket_kernel(const void* __restrict__ ei_raw,
                                     const void* __restrict__ et_raw) {
    int e = blockIdx.x * blockDim.x + threadIdx.x;
    if (e >= N_EDGES) return;
    int src, dst, et;
    if (g_is64) {
        const long long* ei = (const long long*)ei_raw;
        const long long* etp = (const long long*)et_raw;
        src = (int)ei[e];
        dst = (int)ei[N_EDGES + e];
        et  = (int)etp[e];
    } else {
        const int* ei = (const int*)ei_raw;
        const int* etp = (const int*)et_raw;
        src = ei[e];
        dst = ei[N_EDGES + e];
        et  = etp[e];
    }
    int slot = atomicAdd(&g_cnt[dst], 1);
    if (slot < BCAP) g_bucket[(size_t)dst * BCAP + slot] = src * 4 + et;
}

__device__ __forceinline__ void ldsm4(uint32_t& r0, uint32_t& r1,
                                      uint32_t& r2, uint32_t& r3, uint32_t addr) {
    asm volatile("ldmatrix.sync.aligned.m8n8.x4.shared.b16 {%0,%1,%2,%3}, [%4];"
                 : "=r"(r0), "=r"(r1), "=r"(r2), "=r"(r3) : "r"(addr));
}

__device__ __forceinline__ void mma_f16(float* c, const uint32_t* a,
                                        uint32_t b0, uint32_t b1) {
    asm volatile("mma.sync.aligned.m16n8k16.row.col.f32.f16.f16.f32 "
                 "{%0,%1,%2,%3}, {%4,%5,%6,%7}, {%8,%9}, {%0,%1,%2,%3};"
                 : "+f"(c[0]), "+f"(c[1]), "+f"(c[2]), "+f"(c[3])
                 : "r"(a[0]), "r"(a[1]), "r"(a[2]), "r"(a[3]), "r"(b0), "r"(b1));
}

// ---------------- GEMM: persistent row-tile, BN=64, 2 CTAs/SM ----------------
#define SMEM_TOT (64 * 1024)
__global__ __launch_bounds__(256, 2) void gemm_hc(const float* __restrict__ x) {
    extern __shared__ __align__(16) char smem[];
    const uint32_t sb = (uint32_t)__cvta_generic_to_shared(smem);
    const int t = threadIdx.x;
    const int lane = t & 31, wid = t >> 5;
    const int wm = wid & 3, wn = wid >> 2;
    const int rowBase = blockIdx.x * 128;

#pragma unroll
    for (int i = 0; i < 8; i++) {
        int u = i * 256 + t;
        int r = u >> 4, c = u & 15;
        int row = rowBase + r;
        float4 v0 = make_float4(0.f, 0.f, 0.f, 0.f), v1 = v0;
        if (row < N_NODES) {
            v0 = *(const float4*)(x + (size_t)row * 128 + c * 8);
            v1 = *(const float4*)(x + (size_t)row * 128 + c * 8 + 4);
        }
        __half2 h0 = __floats2half2_rn(v0.x, v0.y);
        __half2 h1 = __floats2half2_rn(v0.z, v0.w);
        __half2 h2 = __floats2half2_rn(v1.x, v1.y);
        __half2 h3 = __floats2half2_rn(v1.z, v1.w);
        uint4 hi = make_uint4(*(uint32_t*)&h0, *(uint32_t*)&h1,
                              *(uint32_t*)&h2, *(uint32_t*)&h3);
        int sw = (c & 8) | ((c & 7) ^ (r & 7));
        *(uint4*)(smem + (r * 16 + sw) * 16) = hi;
    }

#pragma unroll
    for (int i = 0; i < 4; i++) {
        int u = i * 256 + t;
        int n = u >> 4, c = u & 15;
        uint32_t dst = sb + (uint32_t)(2048 + n * 16 + ((c & 8) | ((c & 7) ^ (n & 7)))) * 16;
        CP_ASYNC16(dst, (const char*)(g_Bh + n * 128 + c * 8));
    }
    CP_COMMIT();

    for (int it = 0; it < 9; it++) {
        if (it < 8) {
            const int nb = (it + 1) & 1;
            const int colN = (it + 1) * 64;
#pragma unroll
            for (int i = 0; i < 4; i++) {
                int u = i * 256 + t;
                int n = u >> 4, c = u & 15;
                uint32_t dst = sb + (uint32_t)(2048 + nb * 1024 + n * 16 +
                                               ((c & 8) | ((c & 7) ^ (n & 7)))) * 16;
                CP_ASYNC16(dst, (const char*)(g_Bh + (colN + n) * 128 + c * 8));
            }
            CP_COMMIT();
            CP_WAIT(1);
        } else {
            CP_WAIT(0);
        }
        __syncthreads();

        const uint32_t bBase = 2048 + (it & 1) * 1024;
        float acc[2][4][4];
#pragma unroll
        for (int mt = 0; mt < 2; mt++)
#pragma unroll
            for (int nt = 0; nt < 4; nt++)
#pragma unroll
                for (int i = 0; i < 4; i++) acc[mt][nt][i] = 0.0f;

#pragma unroll
        for (int s = 0; s < 8; s++) {
            uint32_t Ah[2][4], Bh[4][2];
            const int mat = lane >> 3;
#pragma unroll
            for (int mt = 0; mt < 2; mt++) {
                int r = wm * 32 + mt * 16 + (mat & 1) * 8 + (lane & 7);
                int c = s * 2 + (mat >> 1);
                int sw = (c & 8) | ((c & 7) ^ (r & 7));
                ldsm4(Ah[mt][0], Ah[mt][1], Ah[mt][2], Ah[mt][3],
                      sb + (uint32_t)(r * 16 + sw) * 16);
            }
#pragma unroll
            for (int p = 0; p < 2; p++) {
                int n = wn * 32 + p * 16 + (mat >> 1) * 8 + (lane & 7);
                int c = s * 2 + (mat & 1);
                int sw = (c & 8) | ((c & 7) ^ (n & 7));
                ldsm4(Bh[p * 2][0], Bh[p * 2][1], Bh[p * 2 + 1][0], Bh[p * 2 + 1][1],
                      sb + (uint32_t)(bBase + n * 16 + sw) * 16);
            }
#pragma unroll
            for (int mt = 0; mt < 2; mt++)
#pragma unroll
                for (int nt = 0; nt < 4; nt++)
                    mma_f16(acc[mt][nt], Ah[mt], Bh[nt][0], Bh[nt][1]);
        }

        const int colBase = it * 64;
#pragma unroll
        for (int mt = 0; mt < 2; mt++) {
            int row0 = rowBase + wm * 32 + mt * 16 + (lane >> 2);
#pragma unroll
            for (int nt = 0; nt < 4; nt++) {
                int lc = wn * 32 + nt * 8 + (lane & 3) * 2;
#pragma unroll
                for (int half = 0; half < 2; half++) {
                    int row = row0 + half * 8;
                    if (row >= N_NODES) continue;
                    float f0 = acc[mt][nt][half * 2];
                    float f1 = acc[mt][nt][half * 2 + 1];
                    if (it < 8) {
                        *(__half2*)(g_xrelh + (size_t)row * 512 + colBase + lc) =
                            __floats2half2_rn(f0, f1);
                    } else {
                        if (lc < 16)
                            *(float2*)(g_s1 + row * 16 + lc) = make_float2(f0, f1);
                        else if (lc < 32)
                            *(float2*)(g_s2 + row * 16 + (lc - 16)) = make_float2(f0, f1);
                    }
                }
            }
        }
        __syncthreads();
    }
}

// ---------------- fused edge pass: all rel-indexed state in smem --------------
// 256 thr = 8 warps, warp per dst. No dynamic register-array indexing anywhere:
// den owned by lanes 0..15 (one (rel,head) each), weights pre-multiplied into
// sm_w so phase B is LDS + LDG + cvt + FMA only.
__global__ __launch_bounds__(256) void edge_fused(float* __restrict__ out) {
    __shared__ int   sm_pk[8][BCAP];
    __shared__ float sm_w[8][BCAP * 4];
    __shared__ float sm_rden[8][16];
    int w = threadIdx.x >> 5;
    int d = blockIdx.x * 8 + w;
    if (d >= N_NODES) return;
    int lane = threadIdx.x & 31;
    int deg = g_cnt[d];
    if (deg > BCAP) deg = BCAP;
    const int* bk = g_bucket + (size_t)d * BCAP;

    // ---- phase A: lane-parallel logits+exp (8 edges x 4 heads per step) ----
    int ie = lane >> 2;
    int hA = lane & 3;
    for (int base = 0; base < deg; base += 8) {
        int i = base + ie;
        if (i < deg) {
            int packed = bk[i];
            float al = g_s1[packed * 4 + hA] + g_s2[d * 16 + (packed & 3) * 4 + hA];
            al = al > 0.f ? al : 0.2f * al;
            sm_w[w][i * 4 + hA] = __expf(al);
            if (hA == 0) sm_pk[w][i] = packed;
        }
    }
    __syncwarp();

    // ---- denominators: lanes 0..15 each own one (rel, head) ----
    if (lane < 16) {
        int rl = lane >> 2, hd = lane & 3;
        float den = 0.0f;
        for (int i = 0; i < deg; i++)
            if ((sm_pk[w][i] & 3) == rl) den += sm_w[w][i * 4 + hd];
        sm_rden[w][lane] = (den > 0.f) ? __frcp_rn(den) : 0.0f;
    }
    __syncwarp();

    // ---- pre-multiply weights into sm_w (lane-parallel) ----
    for (int base = 0; base < deg; base += 8) {
        int i = base + ie;
        if (i < deg) {
            int et = sm_pk[w][i] & 3;
            sm_w[w][i * 4 + hA] *= sm_rden[w][et * 4 + hA];
        }
    }
    __syncwarp();

    // ---- phase B: pure weighted gather-accumulate (MLP-4) ----
    int h = lane >> 3;
    float a0 = 0.f, a1 = 0.f, a2 = 0.f, a3 = 0.f;
    const uint2* xr = reinterpret_cast<const uint2*>(g_xrelh) + lane;
    int i = 0;
    for (; i + 4 <= deg; i += 4) {
        unsigned o0 = (unsigned)sm_pk[w][i] * 32u;
        unsigned o1 = (unsigned)sm_pk[w][i + 1] * 32u;
        unsigned o2 = (unsigned)sm_pk[w][i + 2] * 32u;
        unsigned o3 = (unsigned)sm_pk[w][i + 3] * 32u;
        uint2 r0 = xr[o0];
        uint2 r1 = xr[o1];
        uint2 r2 = xr[o2];
        uint2 r3 = xr[o3];
        float w0 = sm_w[w][(i + 0) * 4 + h];
        float w1 = sm_w[w][(i + 1) * 4 + h];
        float w2 = sm_w[w][(i + 2) * 4 + h];
        float w3 = sm_w[w][(i + 3) * 4 + h];
        float2 f;
        f = __half22float2(*(__half2*)&r0.x); a0 += f.x * w0; a1 += f.y * w0;
        f = __half22float2(*(__half2*)&r0.y); a2 += f.x * w0; a3 += f.y * w0;
        f = __half22float2(*(__half2*)&r1.x); a0 += f.x * w1; a1 += f.y * w1;
        f = __half22float2(*(__half2*)&r1.y); a2 += f.x * w1; a3 += f.y * w1;
        f = __half22float2(*(__half2*)&r2.x); a0 += f.x * w2; a1 += f.y * w2;
        f = __half22float2(*(__half2*)&r2.y); a2 += f.x * w2; a3 += f.y * w2;
        f = __half22float2(*(__half2*)&r3.x); a0 += f.x * w3; a1 += f.y * w3;
        f = __half22float2(*(__half2*)&r3.y); a2 += f.x * w3; a3 += f.y * w3;
    }
    for (; i < deg; i++) {
        unsigned o = (unsigned)sm_pk[w][i] * 32u;
        float wgt = sm_w[w][i * 4 + h];
        uint2 raw = xr[o];
        float2 f0 = __half22float2(*(__half2*)&raw.x);
        float2 f1 = __half22float2(*(__half2*)&raw.y);
        a0 += f0.x * wgt; a1 += f0.y * wgt; a2 += f1.x * wgt; a3 += f1.y * wgt;
    }
    reinterpret_cast<float4*>(out + (size_t)d * 128)[lane] = make_float4(a0, a1, a2, a3);
}

// ---------------- launch ----------------
extern "C" void kernel_launch(void* const* d_in, const int* in_sizes, int n_in,
                              void* d_out, int out_size) {
    const float* x    = (const float*)d_in[0];
    const void*  ei   = d_in[1];
    const void*  etyp = d_in[2];
    const float* W    = (const float*)d_in[3];
    const float* attn = (const float*)d_in[4];
    float*       out  = (float*)d_out;

    cudaFuncSetAttribute(gemm_hc, cudaFuncAttributeMaxDynamicSharedMemorySize, SMEM_TOT);

    int zblocks = (N_NODES + 255) / 256;
    prep_detect_zero<<<PREP_BLOCKS + zblocks, 256>>>(W, attn, (const unsigned*)ei);
    decode_bucket_kernel<<<(N_EDGES + 255) / 256, 256>>>(ei, etyp);
    gemm_hc<<<(N_NODES + 127) / 128, 256, SMEM_TOT>>>(x);
    edge_fused<<<(N_NODES + 7) / 8, 256>>>(out);
}

// round 16
// speedup vs baseline: 1.2780x; 1.0420x over previous
#include <cuda_runtime.h>
#include <cuda_fp16.h>
#include <cstdint>

// ---------------- problem constants ----------------
#define N_NODES 100000
#define N_EDGES 600000
#define NCOLS 544            // 512 xrel + 16 s1 + 16 s2
#define NPAD 576             // padded to 9 * 64-col tiles
#define BCAP 48              // bucket capacity per dst (Poisson(6), max ~25)

// ---------------- device scratch (no allocs allowed) ----------------
__device__ __align__(16) __half g_Bh[NPAD * 128];              // B fp16 [j][k]
__device__ __align__(16) __half g_xrelh[(size_t)N_NODES * 512];// [(n*4+r)][128] fp16
__device__ __align__(16) float g_s1[N_NODES * 16];             // [n][r][h]
__device__ __align__(16) float g_s2[N_NODES * 16];             // [n][r][h]
__device__ int g_cnt[N_NODES];                                 // per-dst degree
__device__ int g_bucket[(size_t)N_NODES * BCAP];               // packed src*4+et
__device__ int g_is64;

#define CP_ASYNC16(dst, src) \
    asm volatile("cp.async.cg.shared.global [%0], [%1], 16;" :: "r"(dst), "l"(src) : "memory")
#define CP_COMMIT()  asm volatile("cp.async.commit_group;" ::: "memory")
#define CP_WAIT(n)   asm volatile("cp.async.wait_group %0;" :: "n"(n) : "memory")

// ---------------- merged prologue ----------------
#define WT_BLOCKS 64
#define AT_BLOCKS 32
#define PREP_BLOCKS (WT_BLOCKS + AT_BLOCKS)
__global__ void prep_detect_zero(const float* __restrict__ W,
                                 const float* __restrict__ attn,
                                 const unsigned* __restrict__ ei) {
    if (blockIdx.x < WT_BLOCKS) {
        __shared__ float tile[32][33];
        int tt = blockIdx.x;
        int r  = tt >> 4;
        int kt = (tt >> 2) & 3;
        int ot = tt & 3;
        int ty = threadIdx.x >> 5;
        int tx = threadIdx.x & 31;
#pragma unroll
        for (int s = 0; s < 4; s++) {
            int k = kt * 32 + ty + s * 8;
            int o = ot * 32 + tx;
            tile[ty + s * 8][tx] = W[(r * 128 + k) * 128 + o];
        }
        __syncthreads();
#pragma unroll
        for (int s = 0; s < 4; s++) {
            int o = ot * 32 + ty + s * 8;
            int k = kt * 32 + tx;
            g_Bh[(r * 128 + o) * 128 + k] = __float2half(tile[tx][ty + s * 8]);
        }
    } else if (blockIdx.x < PREP_BLOCKS) {
        int id = (blockIdx.x - WT_BLOCKS) * 256 + threadIdx.x;
        int j2 = id >> 7;
        int k = id & 127;
        float v = 0.0f;
        if (j2 < 32) {
            int half = j2 >> 4;
            int rh = j2 & 15;
            int r = rh >> 2, h = rh & 3;
            const float* wp = W + (r * 128 + k) * 128 + h * 32;
            const float* ap = attn + rh * 64 + half * 32;
            float s = 0.0f;
#pragma unroll
            for (int d = 0; d < 32; d++) s += wp[d] * ap[d];
            v = s;
        }
        g_Bh[(512 + j2) * 128 + k] = __float2half(v);
    } else {
        int i = (blockIdx.x - PREP_BLOCKS) * 256 + threadIdx.x;
        if (i < N_NODES) g_cnt[i] = 0;
        if (i == 0) {
            int is64 = 1;
            for (int k = 0; k < 16; k++)
                if (ei[2 * k + 1] != 0u) is64 = 0;
            g_is64 = is64;
        }
    }
}

// ---------------- decode + bucket ----------------
__global__ void decode_bucket_kernel(const void* __restrict__ ei_raw,
                                     const void* __restrict__ et_raw) {
    int e = blockIdx.x * blockDim.x + threadIdx.x;
    if (e >= N_EDGES) return;
    int src, dst, et;
    if (g_is64) {
        const long long* ei = (const long long*)ei_raw;
        const long long* etp = (const long long*)et_raw;
        src = (int)ei[e];
        dst = (int)ei[N_EDGES + e];
        et  = (int)etp[e];
    } else {
        const int* ei = (const int*)ei_raw;
        const int* etp = (const int*)et_raw;
        src = ei[e];
        dst = ei[N_EDGES + e];
        et  = etp[e];
    }
    int slot = atomicAdd(&g_cnt[dst], 1);
    if (slot < BCAP) g_bucket[(size_t)dst * BCAP + slot] = src * 4 + et;
}

__device__ __forceinline__ void ldsm4(uint32_t& r0, uint32_t& r1,
                                      uint32_t& r2, uint32_t& r3, uint32_t addr) {
    asm volatile("ldmatrix.sync.aligned.m8n8.x4.shared.b16 {%0,%1,%2,%3}, [%4];"
                 : "=r"(r0), "=r"(r1), "=r"(r2), "=r"(r3) : "r"(addr));
}

__device__ __forceinline__ void mma_f16(float* c, const uint32_t* a,
                                        uint32_t b0, uint32_t b1) {
    asm volatile("mma.sync.aligned.m16n8k16.row.col.f32.f16.f16.f32 "
                 "{%0,%1,%2,%3}, {%4,%5,%6,%7}, {%8,%9}, {%0,%1,%2,%3};"
                 : "+f"(c[0]), "+f"(c[1]), "+f"(c[2]), "+f"(c[3])
                 : "r"(a[0]), "r"(a[1]), "r"(a[2]), "r"(a[3]), "r"(b0), "r"(b1));
}

// ---------------- GEMM: A fragments hoisted to registers --------------------
// grid=782, 256 thr (4 m-warps x 2 n-warps, 32x32 warp tile), BN=64, 9 iters.
// A fp16 in smem only during the fragment-load prologue; fragments live in
// Areg[8][2][4] (64 regs) across all 9 col-iters -> per-iter LDSM halved.
#define SMEM_TOT (64 * 1024)
__global__ __launch_bounds__(256, 2) void gemm_hc(const float* __restrict__ x) {
    extern __shared__ __align__(16) char smem[];
    const uint32_t sb = (uint32_t)__cvta_generic_to_shared(smem);
    const int t = threadIdx.x;
    const int lane = t & 31, wid = t >> 5;
    const int wm = wid & 3, wn = wid >> 2;
    const int rowBase = blockIdx.x * 128;

    // ---- load + convert A tile (128 x 128) into smem ----
#pragma unroll
    for (int i = 0; i < 8; i++) {
        int u = i * 256 + t;
        int r = u >> 4, c = u & 15;
        int row = rowBase + r;
        float4 v0 = make_float4(0.f, 0.f, 0.f, 0.f), v1 = v0;
        if (row < N_NODES) {
            v0 = *(const float4*)(x + (size_t)row * 128 + c * 8);
            v1 = *(const float4*)(x + (size_t)row * 128 + c * 8 + 4);
        }
        __half2 h0 = __floats2half2_rn(v0.x, v0.y);
        __half2 h1 = __floats2half2_rn(v0.z, v0.w);
        __half2 h2 = __floats2half2_rn(v1.x, v1.y);
        __half2 h3 = __floats2half2_rn(v1.z, v1.w);
        uint4 hi = make_uint4(*(uint32_t*)&h0, *(uint32_t*)&h1,
                              *(uint32_t*)&h2, *(uint32_t*)&h3);
        int sw = (c & 8) | ((c & 7) ^ (r & 7));
        *(uint4*)(smem + (r * 16 + sw) * 16) = hi;
    }

    // ---- issue B tile 0 ----
#pragma unroll
    for (int i = 0; i < 4; i++) {
        int u = i * 256 + t;
        int n = u >> 4, c = u & 15;
        uint32_t dst = sb + (uint32_t)(2048 + n * 16 + ((c & 8) | ((c & 7) ^ (n & 7)))) * 16;
        CP_ASYNC16(dst, (const char*)(g_Bh + n * 128 + c * 8));
    }
    CP_COMMIT();
    __syncthreads();     // A smem complete

    // ---- hoist all A fragments into registers (64 regs) ----
    uint32_t Areg[8][2][4];
    {
        const int mat = lane >> 3;
#pragma unroll
        for (int s = 0; s < 8; s++)
#pragma unroll
            for (int mt = 0; mt < 2; mt++) {
                int r = wm * 32 + mt * 16 + (mat & 1) * 8 + (lane & 7);
                int c = s * 2 + (mat >> 1);
                int sw = (c & 8) | ((c & 7) ^ (r & 7));
                ldsm4(Areg[s][mt][0], Areg[s][mt][1], Areg[s][mt][2], Areg[s][mt][3],
                      sb + (uint32_t)(r * 16 + sw) * 16);
            }
    }

    for (int it = 0; it < 9; it++) {
        if (it < 8) {
            const int nb = (it + 1) & 1;
            const int colN = (it + 1) * 64;
#pragma unroll
            for (int i = 0; i < 4; i++) {
                int u = i * 256 + t;
                int n = u >> 4, c = u & 15;
                uint32_t dst = sb + (uint32_t)(2048 + nb * 1024 + n * 16 +
                                               ((c & 8) | ((c & 7) ^ (n & 7)))) * 16;
                CP_ASYNC16(dst, (const char*)(g_Bh + (colN + n) * 128 + c * 8));
            }
            CP_COMMIT();
            CP_WAIT(1);
        } else {
            CP_WAIT(0);
        }
        __syncthreads();

        const uint32_t bBase = 2048 + (it & 1) * 1024;
        float acc[2][4][4];
#pragma unroll
        for (int mt = 0; mt < 2; mt++)
#pragma unroll
            for (int nt = 0; nt < 4; nt++)
#pragma unroll
                for (int i = 0; i < 4; i++) acc[mt][nt][i] = 0.0f;

#pragma unroll
        for (int s = 0; s < 8; s++) {
            uint32_t Bh[4][2];
            const int mat = lane >> 3;
#pragma unroll
            for (int p = 0; p < 2; p++) {
                int n = wn * 32 + p * 16 + (mat >> 1) * 8 + (lane & 7);
                int c = s * 2 + (mat & 1);
                int sw = (c & 8) | ((c & 7) ^ (n & 7));
                ldsm4(Bh[p * 2][0], Bh[p * 2][1], Bh[p * 2 + 1][0], Bh[p * 2 + 1][1],
                      sb + (uint32_t)(bBase + n * 16 + sw) * 16);
            }
#pragma unroll
            for (int mt = 0; mt < 2; mt++)
#pragma unroll
                for (int nt = 0; nt < 4; nt++)
                    mma_f16(acc[mt][nt], Areg[s][mt], Bh[nt][0], Bh[nt][1]);
        }

        // ---- epilogue for this 64-col tile ----
        const int colBase = it * 64;
#pragma unroll
        for (int mt = 0; mt < 2; mt++) {
            int row0 = rowBase + wm * 32 + mt * 16 + (lane >> 2);
#pragma unroll
            for (int nt = 0; nt < 4; nt++) {
                int lc = wn * 32 + nt * 8 + (lane & 3) * 2;
#pragma unroll
                for (int half = 0; half < 2; half++) {
                    int row = row0 + half * 8;
                    if (row >= N_NODES) continue;
                    float f0 = acc[mt][nt][half * 2];
                    float f1 = acc[mt][nt][half * 2 + 1];
                    if (it < 8) {
                        *(__half2*)(g_xrelh + (size_t)row * 512 + colBase + lc) =
                            __floats2half2_rn(f0, f1);
                    } else {
                        if (lc < 16)
                            *(float2*)(g_s1 + row * 16 + lc) = make_float2(f0, f1);
                        else if (lc < 32)
                            *(float2*)(g_s2 + row * 16 + (lc - 16)) = make_float2(f0, f1);
                    }
                }
            }
        }
        __syncthreads();
    }
}

// ---------------- fused edge pass: all rel-indexed state in smem --------------
__global__ __launch_bounds__(256) void edge_fused(float* __restrict__ out) {
    __shared__ int   sm_pk[8][BCAP];
    __shared__ float sm_w[8][BCAP * 4];
    __shared__ float sm_rden[8][16];
    int w = threadIdx.x >> 5;
    int d = blockIdx.x * 8 + w;
    if (d >= N_NODES) return;
    int lane = threadIdx.x & 31;
    int deg = g_cnt[d];
    if (deg > BCAP) deg = BCAP;
    const int* bk = g_bucket + (size_t)d * BCAP;

    int ie = lane >> 2;
    int hA = lane & 3;
    for (int base = 0; base < deg; base += 8) {
        int i = base + ie;
        if (i < deg) {
            int packed = bk[i];
            float al = g_s1[packed * 4 + hA] + g_s2[d * 16 + (packed & 3) * 4 + hA];
            al = al > 0.f ? al : 0.2f * al;
            sm_w[w][i * 4 + hA] = __expf(al);
            if (hA == 0) sm_pk[w][i] = packed;
        }
    }
    __syncwarp();

    if (lane < 16) {
        int rl = lane >> 2, hd = lane & 3;
        float den = 0.0f;
        for (int i = 0; i < deg; i++)
            if ((sm_pk[w][i] & 3) == rl) den += sm_w[w][i * 4 + hd];
        sm_rden[w][lane] = (den > 0.f) ? __frcp_rn(den) : 0.0f;
    }
    __syncwarp();

    for (int base = 0; base < deg; base += 8) {
        int i = base + ie;
        if (i < deg) {
            int et = sm_pk[w][i] & 3;
            sm_w[w][i * 4 + hA] *= sm_rden[w][et * 4 + hA];
        }
    }
    __syncwarp();

    int h = lane >> 3;
    float a0 = 0.f, a1 = 0.f, a2 = 0.f, a3 = 0.f;
    const uint2* xr = reinterpret_cast<const uint2*>(g_xrelh) + lane;
    int i = 0;
    for (; i + 4 <= deg; i += 4) {
        unsigned o0 = (unsigned)sm_pk[w][i] * 32u;
        unsigned o1 = (unsigned)sm_pk[w][i + 1] * 32u;
        unsigned o2 = (unsigned)sm_pk[w][i + 2] * 32u;
        unsigned o3 = (unsigned)sm_pk[w][i + 3] * 32u;
        uint2 r0 = xr[o0];
        uint2 r1 = xr[o1];
        uint2 r2 = xr[o2];
        uint2 r3 = xr[o3];
        float w0 = sm_w[w][(i + 0) * 4 + h];
        float w1 = sm_w[w][(i + 1) * 4 + h];
        float w2 = sm_w[w][(i + 2) * 4 + h];
        float w3 = sm_w[w][(i + 3) * 4 + h];
        float2 f;
        f = __half22float2(*(__half2*)&r0.x); a0 += f.x * w0; a1 += f.y * w0;
        f = __half22float2(*(__half2*)&r0.y); a2 += f.x * w0; a3 += f.y * w0;
        f = __half22float2(*(__half2*)&r1.x); a0 += f.x * w1; a1 += f.y * w1;
        f = __half22float2(*(__half2*)&r1.y); a2 += f.x * w1; a3 += f.y * w1;
        f = __half22float2(*(__half2*)&r2.x); a0 += f.x * w2; a1 += f.y * w2;
        f = __half22float2(*(__half2*)&r2.y); a2 += f.x * w2; a3 += f.y * w2;
        f = __half22float2(*(__half2*)&r3.x); a0 += f.x * w3; a1 += f.y * w3;
        f = __half22float2(*(__half2*)&r3.y); a2 += f.x * w3; a3 += f.y * w3;
    }
    for (; i < deg; i++) {
        unsigned o = (unsigned)sm_pk[w][i] * 32u;
        float wgt = sm_w[w][i * 4 + h];
        uint2 raw = xr[o];
        float2 f0 = __half22float2(*(__half2*)&raw.x);
        float2 f1 = __half22float2(*(__half2*)&raw.y);
        a0 += f0.x * wgt; a1 += f0.y * wgt; a2 += f1.x * wgt; a3 += f1.y * wgt;
    }
    reinterpret_cast<float4*>(out + (size_t)d * 128)[lane] = make_float4(a0, a1, a2, a3);
}

// ---------------- launch ----------------
extern "C" void kernel_launch(void* const* d_in, const int* in_sizes, int n_in,
                              void* d_out, int out_size) {
    const float* x    = (const float*)d_in[0];
    const void*  ei   = d_in[1];
    const void*  etyp = d_in[2];
    const float* W    = (const float*)d_in[3];
    const float* attn = (const float*)d_in[4];
    float*       out  = (float*)d_out;

    cudaFuncSetAttribute(gemm_hc, cudaFuncAttributeMaxDynamicSharedMemorySize, SMEM_TOT);

    int zblocks = (N_NODES + 255) / 256;
    prep_detect_zero<<<PREP_BLOCKS + zblocks, 256>>>(W, attn, (const unsigned*)ei);
    decode_bucket_kernel<<<(N_EDGES + 255) / 256, 256>>>(ei, etyp);
    gemm_hc<<<(N_NODES + 127) / 128, 256, SMEM_TOT>>>(x);
    edge_fused<<<(N_NODES + 7) / 8, 256>>>(out);
}